// round 13
// baseline (speedup 1.0000x reference)
#include <cuda_runtime.h>
#include <cuda_fp16.h>
#include <math.h>
#include <stdint.h>

#define BC   4
#define MC   32
#define DKC  256
#define DVC  32
#define PC   4096

// ---------------- scratch ----------------
__device__ __half g_q16 [BC * DKC * PC];      // q proj (fp16)
__device__ __half g_k416[BC * DKC * PC];      // k proj frames 0..3 (fp16)
__device__ float  g_v4  [BC * DVC * PC];
__device__ float  g_part[2 * BC * MC * PC];   // split-d partial scores
__device__ __half g_f16 [BC * DKC * PC];
__device__ __half g_w16 [2 * DKC * DKC];

// ---------------- PTX helpers ----------------
__device__ __forceinline__ uint32_t smem_u32(const void* p) {
    return (uint32_t)__cvta_generic_to_shared(p);
}
#define CP_ASYNC16(dst, src) \
    asm volatile("cp.async.cg.shared.global [%0], [%1], 16;\n" :: "r"(dst), "l"(src))
#define CP_COMMIT() asm volatile("cp.async.commit_group;\n")
#define CP_WAITN(n) asm volatile("cp.async.wait_group %0;\n" :: "n"(n) : "memory")

#define LDSM_X4(r0,r1,r2,r3,addr) \
    asm volatile("ldmatrix.sync.aligned.m8n8.x4.shared.b16 {%0,%1,%2,%3}, [%4];" \
        : "=r"(r0),"=r"(r1),"=r"(r2),"=r"(r3) : "r"(addr))
#define LDSM_X4_T(r0,r1,r2,r3,addr) \
    asm volatile("ldmatrix.sync.aligned.m8n8.x4.trans.shared.b16 {%0,%1,%2,%3}, [%4];" \
        : "=r"(r0),"=r"(r1),"=r"(r2),"=r"(r3) : "r"(addr))
#define MMA16816(c0,c1,c2,c3,a0,a1,a2,a3,b0,b1) \
    asm volatile("mma.sync.aligned.m16n8k16.row.col.f32.f16.f16.f32 " \
        "{%0,%1,%2,%3},{%4,%5,%6,%7},{%8,%9},{%0,%1,%2,%3};" \
        : "+f"(c0),"+f"(c1),"+f"(c2),"+f"(c3) \
        : "r"(a0),"r"(a1),"r"(a2),"r"(a3),"r"(b0),"r"(b1))

// ---------------------------------------------------------------------------
// prep: convert_fc (blocks 0..2047) + convert_w (2048..2303) +
//       proj_v (2304..2815). Independent -> concurrent.
// ---------------------------------------------------------------------------
__global__ __launch_bounds__(256) void prep_kernel(
    const float* __restrict__ fc, const float* __restrict__ Qw,
    const float* __restrict__ Kw, const float* __restrict__ fm,
    const float* __restrict__ Vw)
{
    __shared__ float Vs[DVC][DVC];
    const int tid = threadIdx.x;
    const int bid = blockIdx.x;

    if (bid < 2048) {
        const size_t base = (size_t)bid * 512 + tid;
#pragma unroll
        for (int r = 0; r < 2; ++r) {
            const size_t gid = base + r * 256;
            float4 v = ((const float4*)fc)[gid];
            __half2 h0, h1;
            h0.x = __float2half_rn(v.x); h0.y = __float2half_rn(v.y);
            h1.x = __float2half_rn(v.z); h1.y = __float2half_rn(v.w);
            ((__half2*)g_f16)[gid * 2]     = h0;
            ((__half2*)g_f16)[gid * 2 + 1] = h1;
        }
    } else if (bid < 2304) {
        const int gid = (bid - 2048) * 256 + tid;
        const int isK = gid >> 15;
        const int rem = gid & 32767;
        const int e = rem >> 7;
        const int d = (rem & 127) * 2;
        const float* W = isK ? Kw : Qw;
        __half2 h;
        h.x = __float2half_rn(W[(size_t)d * DKC + e]);
        h.y = __float2half_rn(W[(size_t)(d + 1) * DKC + e]);
        ((__half2*)g_w16)[((size_t)isK * 65536 + (size_t)e * 256 + d) >> 1] = h;
    } else {
        for (int i = tid; i < DVC * DVC; i += 256) Vs[i >> 5][i & 31] = Vw[i];
        __syncthreads();

        const int gid = (bid - 2304) * 256 + tid;
        const int eg = gid >> 14;
        const int b = (gid >> 12) & 3;
        const int p = gid & (PC - 1);

        float f[DVC];
        const float* fmp = fm + (size_t)b * DVC * PC + p;
#pragma unroll
        for (int d = 0; d < DVC; ++d) f[d] = fmp[(size_t)d * PC];

        float* vo = g_v4 + (size_t)b * DVC * PC + p;
#pragma unroll
        for (int ee = 0; ee < 4; ++ee) {
            const int e = eg * 4 + ee;
            float a = 0.f;
#pragma unroll
            for (int d = 0; d < DVC; ++d) a += f[d] * Vs[d][e];
            vo[(size_t)e * PC] = a;
        }
    }
}

// ---------------------------------------------------------------------------
// fp16 HMMA GEMM: Out[e,p] = sum_d W[d,e] * X[d,p]. fp16 output.
// BM=128, BN=256, BK=64, 4-stage full prefetch.
// ---------------------------------------------------------------------------
#define AROW 72
#define BROW 264
#define A_STAGE (128 * AROW)
#define B_STAGE (64 * BROW)
#define STAGE_ELEMS (A_STAGE + B_STAGE)
#define GEMM_SMEM_BYTES (4 * STAGE_ELEMS * 2)

__device__ __forceinline__ void gemm_load_stage(
    __half* stg, int s, int tid, int isK, int e0, int b, int p0)
{
    const int d0 = s * 64;
    const __half* Ag = g_w16 + (size_t)isK * 65536 + (size_t)e0 * 256 + d0;
    const __half* Bg = g_f16 + (size_t)b * (DKC * PC) + (size_t)d0 * PC + p0;
    __half* As = stg;
    __half* Bs = stg + A_STAGE;
#pragma unroll
    for (int i = 0; i < 4; ++i) {
        const int c = tid + i * 256;
        const int row = c >> 3, col = c & 7;
        CP_ASYNC16(smem_u32(&As[row * AROW + col * 8]),
                   Ag + (size_t)row * 256 + col * 8);
    }
#pragma unroll
    for (int i = 0; i < 8; ++i) {
        const int c = tid + i * 256;
        const int row = c >> 5, col = c & 31;
        CP_ASYNC16(smem_u32(&Bs[row * BROW + col * 8]),
                   Bg + (size_t)row * PC + col * 8);
    }
    CP_COMMIT();
}

__global__ void __launch_bounds__(256) gemm_hmma_kernel()
{
    extern __shared__ __half sm[];
    const int tid = threadIdx.x, wid = tid >> 5, lane = tid & 31;
    const int p0 = blockIdx.x * 256;
    const int y = blockIdx.y;
    const int isK = y >> 1;
    const int e0 = (y & 1) * 128;
    const int b = blockIdx.z;

    const int ew = (wid >> 2) * 64;
    const int pw = (wid & 3) * 64;

    float acc[4][8][4];
#pragma unroll
    for (int mt = 0; mt < 4; ++mt)
#pragma unroll
        for (int nt = 0; nt < 8; ++nt)
#pragma unroll
            for (int i = 0; i < 4; ++i) acc[mt][nt][i] = 0.f;

    gemm_load_stage(sm,                   0, tid, isK, e0, b, p0);
    gemm_load_stage(sm + STAGE_ELEMS,     1, tid, isK, e0, b, p0);
    gemm_load_stage(sm + 2 * STAGE_ELEMS, 2, tid, isK, e0, b, p0);
    gemm_load_stage(sm + 3 * STAGE_ELEMS, 3, tid, isK, e0, b, p0);

#pragma unroll 1
    for (int s = 0; s < 4; ++s) {
        if (s == 0)      { CP_WAITN(3); }
        else if (s == 1) { CP_WAITN(2); }
        else if (s == 2) { CP_WAITN(1); }
        else             { CP_WAITN(0); }
        __syncthreads();

        __half* As = sm + s * STAGE_ELEMS;
        __half* Bs = As + A_STAGE;

#pragma unroll
        for (int ks = 0; ks < 4; ++ks) {
            const int k16 = ks * 16;
            uint32_t a[4][4];
#pragma unroll
            for (int mt = 0; mt < 4; ++mt) {
                uint32_t ad = smem_u32(&As[(ew + mt * 16 + (lane & 15)) * AROW
                                           + k16 + (lane >> 4) * 8]);
                LDSM_X4(a[mt][0], a[mt][1], a[mt][2], a[mt][3], ad);
            }
#pragma unroll
            for (int n2 = 0; n2 < 4; ++n2) {
                uint32_t bf[4];
                uint32_t bd = smem_u32(&Bs[(k16 + (lane & 15)) * BROW
                                           + pw + n2 * 16 + (lane >> 4) * 8]);
                LDSM_X4_T(bf[0], bf[1], bf[2], bf[3], bd);
#pragma unroll
                for (int mt = 0; mt < 4; ++mt) {
                    MMA16816(acc[mt][n2*2][0], acc[mt][n2*2][1],
                             acc[mt][n2*2][2], acc[mt][n2*2][3],
                             a[mt][0], a[mt][1], a[mt][2], a[mt][3],
                             bf[0], bf[1]);
                    MMA16816(acc[mt][n2*2+1][0], acc[mt][n2*2+1][1],
                             acc[mt][n2*2+1][2], acc[mt][n2*2+1][3],
                             a[mt][0], a[mt][1], a[mt][2], a[mt][3],
                             bf[2], bf[3]);
                }
            }
        }
    }

    __half* Out = (isK ? g_k416 : g_q16) + (size_t)b * (DKC * PC);
#pragma unroll
    for (int mt = 0; mt < 4; ++mt) {
#pragma unroll
        for (int nt = 0; nt < 8; ++nt) {
            const int r = e0 + ew + mt * 16 + (lane >> 2);
            const int c = p0 + pw + nt * 8 + (lane & 3) * 2;
            __half2 v0; v0.x = __float2half_rn(acc[mt][nt][0]);
                        v0.y = __float2half_rn(acc[mt][nt][1]);
            __half2 v1; v1.x = __float2half_rn(acc[mt][nt][2]);
                        v1.y = __float2half_rn(acc[mt][nt][3]);
            *(__half2*)&Out[(size_t)r * PC + c]       = v0;
            *(__half2*)&Out[(size_t)(r + 8) * PC + c] = v1;
        }
    }
}

// ---------------------------------------------------------------------------
// scores phase A: partial dot over half of d. grid (64 h, 4 mq, 2 dh).
// q fp16 (staged to fp32 smem); k fp16 for m<4, fp32 buffer for m>=4.
// ---------------------------------------------------------------------------
__global__ __launch_bounds__(256) void scores_partial_kernel(
    const float* __restrict__ kbuf)
{
    __shared__ float qs[32 * 4 * 64];    // [d'][b][w]  32KB

    const int tid = threadIdx.x;
    const int h = blockIdx.x;
    const int mq = blockIdx.y;
    const int dh = blockIdx.z;
    const int w = tid & 63;
    const int mg = tid >> 6;
    const int p = h * 64 + w;
    const int m0 = mq * 8 + mg * 2;
    const int dbase = dh * 128;

    const __half* kh[2] = {nullptr, nullptr};
    const float*  kf[2] = {nullptr, nullptr};
#pragma unroll
    for (int j = 0; j < 2; ++j) {
        const int m = m0 + j;
        if (m < BC) kh[j] = g_k416 + (size_t)m * (DKC * PC) + (size_t)dbase * PC + p;
        else        kf[j] = kbuf + (size_t)(m - BC) * (DKC * PC) + (size_t)dbase * PC + p;
    }
    const bool is16 = (m0 < BC);

    float S[4][2];
#pragma unroll
    for (int bb = 0; bb < 4; ++bb) { S[bb][0] = 0.f; S[bb][1] = 0.f; }

    for (int dc = 0; dc < 4; ++dc) {
        __syncthreads();
        // stage q chunk: 32 d x 4 b x 64 w from fp16, as floats
#pragma unroll
        for (int i = 0; i < 8; ++i) {
            const int flat = (i * 256 + tid) * 4;
            const int d_ = flat >> 8, bb = (flat >> 6) & 3, w0 = flat & 63;
            const __half2* src = (const __half2*)&g_q16[
                ((size_t)(bb * DKC + dbase + dc * 32 + d_)) * PC + h * 64 + w0];
            __half2 a = src[0], bqh = src[1];
            float2 fa = __half22float2(a), fb = __half22float2(bqh);
            qs[flat]     = fa.x; qs[flat + 1] = fa.y;
            qs[flat + 2] = fb.x; qs[flat + 3] = fb.y;
        }
        __syncthreads();
#pragma unroll 8
        for (int d_ = 0; d_ < 32; ++d_) {
            const size_t off = (size_t)(dc * 32 + d_) * PC;
            float kv0, kv1;
            if (is16) { kv0 = __half2float(kh[0][off]); kv1 = __half2float(kh[1][off]); }
            else      { kv0 = kf[0][off];               kv1 = kf[1][off]; }
#pragma unroll
            for (int bb = 0; bb < 4; ++bb) {
                const float qv = qs[(d_ * 4 + bb) * 64 + w];
                S[bb][0] += qv * kv0;
                S[bb][1] += qv * kv1;
            }
        }
    }

#pragma unroll
    for (int bb = 0; bb < 4; ++bb)
#pragma unroll
        for (int j = 0; j < 2; ++j)
            g_part[(((size_t)dh * BC + bb) * MC + m0 + j) * PC + p] = S[bb][j];
}

// ---------------------------------------------------------------------------
// fused merge + softmax + ctx + blend.
// grid (64 pc, 4 dg): block owns h-row pc (w=64 = full softmax group) and
// 8 d's. 256 thr = (w 64, dl 4), each dl handles 2 d.
// ---------------------------------------------------------------------------
__global__ __launch_bounds__(256) void ctx_softmax_kernel(
    const float* __restrict__ vbuf, const float* __restrict__ fm,
    float* __restrict__ out, float scale)
{
    __shared__ float sS[128 * 65];       // [row=bb*32+m][w], padded
    __shared__ float sMx[128], sInv[128];

    const int pc = blockIdx.x, dg = blockIdx.y;
    const int p0 = pc * 64;
    const int tid = threadIdx.x;

    // merge the two d-half partials, scale
#pragma unroll
    for (int i = 0; i < 8; ++i) {
        const int idx = i * 256 + tid;            // 0..2047
        const int row = idx >> 4, c4 = (idx & 15) * 4;
        float4 a = *(const float4*)&g_part[(size_t)row * PC + p0 + c4];
        float4 b = *(const float4*)&g_part[(size_t)(128 + row) * PC + p0 + c4];
        float* drow = &sS[row * 65 + c4];
        drow[0] = (a.x + b.x) * scale;
        drow[1] = (a.y + b.y) * scale;
        drow[2] = (a.z + b.z) * scale;
        drow[3] = (a.w + b.w) * scale;
    }
    __syncthreads();

    // per-row softmax stats (one thread per row)
    if (tid < 128) {
        const float* r = &sS[tid * 65];
        float mx = -1e30f;
#pragma unroll
        for (int i = 0; i < 64; ++i) mx = fmaxf(mx, r[i]);
        float s = 0.f;
#pragma unroll
        for (int i = 0; i < 64; ++i) s += __expf(r[i] - mx);
        sMx[tid] = mx; sInv[tid] = 1.f / s;
    }
    __syncthreads();

    // normalize in place
#pragma unroll
    for (int i = 0; i < 32; ++i) {
        const int idx = i * 256 + tid;            // 0..8191
        const int row = idx >> 6, ww = idx & 63;
        sS[row * 65 + ww] = __expf(sS[row * 65 + ww] - sMx[row]) * sInv[row];
    }
    __syncthreads();

    // ctx
    const int w = tid & 63, dl = tid >> 6;
    const int d0 = dg * 8 + dl * 2;
    const int p = p0 + w;

    float c[4][2];
#pragma unroll
    for (int bb = 0; bb < 4; ++bb) { c[bb][0] = 0.f; c[bb][1] = 0.f; }

#pragma unroll
    for (int m = 0; m < MC; ++m) {
        const float* vsrc = (m < BC) ? (g_v4 + (size_t)m * DVC * PC)
                                     : (vbuf + (size_t)(m - BC) * DVC * PC);
        const float vv0 = vsrc[(size_t)d0 * PC + p];
        const float vv1 = vsrc[(size_t)(d0 + 1) * PC + p];
#pragma unroll
        for (int bb = 0; bb < 4; ++bb) {
            const float a = sS[(bb * MC + m) * 65 + w];
            c[bb][0] += a * vv0;
            c[bb][1] += a * vv1;
        }
    }

#pragma unroll
    for (int bb = 0; bb < 4; ++bb)
#pragma unroll
        for (int j = 0; j < 2; ++j) {
            const size_t o = ((size_t)bb * DVC + d0 + j) * PC + p;
            out[o] = fm[o] + 0.5f * c[bb][j];
        }
}

// ---------------------------------------------------------------------------
extern "C" void kernel_launch(void* const* d_in, const int* in_sizes, int n_in,
                              void* d_out, int out_size)
{
    (void)in_sizes; (void)n_in; (void)out_size;
    const float* fc = (const float*)d_in[0];
    const float* fm = (const float*)d_in[1];
    const float* kb = (const float*)d_in[2];
    const float* vb = (const float*)d_in[3];
    const float* Qw = (const float*)d_in[4];
    const float* Kw = (const float*)d_in[5];
    const float* Vw = (const float*)d_in[6];
    float* out = (float*)d_out;

    const float scale = (float)(log(135168.0) / log(1000.0) / 16.0);

    cudaFuncSetAttribute(gemm_hmma_kernel,
                         cudaFuncAttributeMaxDynamicSharedMemorySize,
                         GEMM_SMEM_BYTES);

    prep_kernel<<<2816, 256>>>(fc, Qw, Kw, fm, Vw);
    gemm_hmma_kernel<<<dim3(16, 4, 4), 256, GEMM_SMEM_BYTES>>>();
    scores_partial_kernel<<<dim3(64, 4, 2), 256>>>(kb);
    ctx_softmax_kernel<<<dim3(64, 4), 256>>>(vb, fm, out, scale);
}

// round 17
// speedup vs baseline: 1.1602x; 1.1602x over previous
#include <cuda_runtime.h>
#include <cuda_fp16.h>
#include <math.h>
#include <stdint.h>

#define BC   4
#define MC   32
#define DKC  256
#define DVC  32
#define PC   4096

// ---------------- scratch ----------------
__device__ float  g_q   [BC * DKC * PC];
__device__ float  g_k4  [BC * DKC * PC];
__device__ float  g_v4  [BC * DVC * PC];
__device__ float  g_part[2 * BC * MC * PC];   // split-d partial scores
__device__ __half g_f16 [BC * DKC * PC];
__device__ __half g_w16 [2 * DKC * DKC];

// ---------------- PTX helpers ----------------
__device__ __forceinline__ uint32_t smem_u32(const void* p) {
    return (uint32_t)__cvta_generic_to_shared(p);
}
#define CP_ASYNC16(dst, src) \
    asm volatile("cp.async.cg.shared.global [%0], [%1], 16;\n" :: "r"(dst), "l"(src))
#define CP_COMMIT() asm volatile("cp.async.commit_group;\n")
#define CP_WAITN(n) asm volatile("cp.async.wait_group %0;\n" :: "n"(n) : "memory")

#define LDSM_X4(r0,r1,r2,r3,addr) \
    asm volatile("ldmatrix.sync.aligned.m8n8.x4.shared.b16 {%0,%1,%2,%3}, [%4];" \
        : "=r"(r0),"=r"(r1),"=r"(r2),"=r"(r3) : "r"(addr))
#define LDSM_X4_T(r0,r1,r2,r3,addr) \
    asm volatile("ldmatrix.sync.aligned.m8n8.x4.trans.shared.b16 {%0,%1,%2,%3}, [%4];" \
        : "=r"(r0),"=r"(r1),"=r"(r2),"=r"(r3) : "r"(addr))
#define MMA16816(c0,c1,c2,c3,a0,a1,a2,a3,b0,b1) \
    asm volatile("mma.sync.aligned.m16n8k16.row.col.f32.f16.f16.f32 " \
        "{%0,%1,%2,%3},{%4,%5,%6,%7},{%8,%9},{%0,%1,%2,%3};" \
        : "+f"(c0),"+f"(c1),"+f"(c2),"+f"(c3) \
        : "r"(a0),"r"(a1),"r"(a2),"r"(a3),"r"(b0),"r"(b1))

// ---------------------------------------------------------------------------
// prep: convert_fc (blocks 0..2047) + convert_w (2048..2303) +
//       proj_v (2304..2815). Independent -> concurrent.
// ---------------------------------------------------------------------------
__global__ __launch_bounds__(256) void prep_kernel(
    const float* __restrict__ fc, const float* __restrict__ Qw,
    const float* __restrict__ Kw, const float* __restrict__ fm,
    const float* __restrict__ Vw)
{
    __shared__ float Vs[DVC][DVC];
    const int tid = threadIdx.x;
    const int bid = blockIdx.x;

    if (bid < 2048) {
        const size_t base = (size_t)bid * 512 + tid;
#pragma unroll
        for (int r = 0; r < 2; ++r) {
            const size_t gid = base + r * 256;
            float4 v = ((const float4*)fc)[gid];
            __half2 h0, h1;
            h0.x = __float2half_rn(v.x); h0.y = __float2half_rn(v.y);
            h1.x = __float2half_rn(v.z); h1.y = __float2half_rn(v.w);
            ((__half2*)g_f16)[gid * 2]     = h0;
            ((__half2*)g_f16)[gid * 2 + 1] = h1;
        }
    } else if (bid < 2304) {
        const int gid = (bid - 2048) * 256 + tid;
        const int isK = gid >> 15;
        const int rem = gid & 32767;
        const int e = rem >> 7;
        const int d = (rem & 127) * 2;
        const float* W = isK ? Kw : Qw;
        __half2 h;
        h.x = __float2half_rn(W[(size_t)d * DKC + e]);
        h.y = __float2half_rn(W[(size_t)(d + 1) * DKC + e]);
        ((__half2*)g_w16)[((size_t)isK * 65536 + (size_t)e * 256 + d) >> 1] = h;
    } else {
        for (int i = tid; i < DVC * DVC; i += 256) Vs[i >> 5][i & 31] = Vw[i];
        __syncthreads();

        const int gid = (bid - 2304) * 256 + tid;
        const int eg = gid >> 14;
        const int b = (gid >> 12) & 3;
        const int p = gid & (PC - 1);

        float f[DVC];
        const float* fmp = fm + (size_t)b * DVC * PC + p;
#pragma unroll
        for (int d = 0; d < DVC; ++d) f[d] = fmp[(size_t)d * PC];

        float* vo = g_v4 + (size_t)b * DVC * PC + p;
#pragma unroll
        for (int ee = 0; ee < 4; ++ee) {
            const int e = eg * 4 + ee;
            float a = 0.f;
#pragma unroll
            for (int d = 0; d < DVC; ++d) a += f[d] * Vs[d][e];
            vo[(size_t)e * PC] = a;
        }
    }
}

// ---------------------------------------------------------------------------
// fp16 HMMA GEMM: Out[e,p] = sum_d W[d,e] * X[d,p]. fp32 output.
// BM=128, BN=256, BK=64, 2-stage double buffer (104KB -> 2 CTA/SM).
// ---------------------------------------------------------------------------
#define AROW 72
#define BROW 264
#define A_STAGE (128 * AROW)
#define B_STAGE (64 * BROW)
#define STAGE_ELEMS (A_STAGE + B_STAGE)
#define GEMM_SMEM_BYTES (2 * STAGE_ELEMS * 2)

__device__ __forceinline__ void gemm_load_stage(
    __half* stg, int s, int tid, int isK, int e0, int b, int p0)
{
    const int d0 = s * 64;
    const __half* Ag = g_w16 + (size_t)isK * 65536 + (size_t)e0 * 256 + d0;
    const __half* Bg = g_f16 + (size_t)b * (DKC * PC) + (size_t)d0 * PC + p0;
    __half* As = stg;
    __half* Bs = stg + A_STAGE;
#pragma unroll
    for (int i = 0; i < 4; ++i) {
        const int c = tid + i * 256;
        const int row = c >> 3, col = c & 7;
        CP_ASYNC16(smem_u32(&As[row * AROW + col * 8]),
                   Ag + (size_t)row * 256 + col * 8);
    }
#pragma unroll
    for (int i = 0; i < 8; ++i) {
        const int c = tid + i * 256;
        const int row = c >> 5, col = c & 31;
        CP_ASYNC16(smem_u32(&Bs[row * BROW + col * 8]),
                   Bg + (size_t)row * PC + col * 8);
    }
    CP_COMMIT();
}

__global__ void __launch_bounds__(256) gemm_hmma_kernel()
{
    extern __shared__ __half sm[];
    const int tid = threadIdx.x, wid = tid >> 5, lane = tid & 31;
    const int p0 = blockIdx.x * 256;
    const int y = blockIdx.y;
    const int isK = y >> 1;
    const int e0 = (y & 1) * 128;
    const int b = blockIdx.z;

    const int ew = (wid >> 2) * 64;
    const int pw = (wid & 3) * 64;

    float acc[4][8][4];
#pragma unroll
    for (int mt = 0; mt < 4; ++mt)
#pragma unroll
        for (int nt = 0; nt < 8; ++nt)
#pragma unroll
            for (int i = 0; i < 4; ++i) acc[mt][nt][i] = 0.f;

    gemm_load_stage(sm,               0, tid, isK, e0, b, p0);
    gemm_load_stage(sm + STAGE_ELEMS, 1, tid, isK, e0, b, p0);

#pragma unroll 1
    for (int s = 0; s < 4; ++s) {
        if (s < 3) { CP_WAITN(1); } else { CP_WAITN(0); }
        __syncthreads();

        __half* As = sm + (s & 1) * STAGE_ELEMS;
        __half* Bs = As + A_STAGE;

#pragma unroll
        for (int ks = 0; ks < 4; ++ks) {
            const int k16 = ks * 16;
            uint32_t a[4][4];
#pragma unroll
            for (int mt = 0; mt < 4; ++mt) {
                uint32_t ad = smem_u32(&As[(ew + mt * 16 + (lane & 15)) * AROW
                                           + k16 + (lane >> 4) * 8]);
                LDSM_X4(a[mt][0], a[mt][1], a[mt][2], a[mt][3], ad);
            }
#pragma unroll
            for (int n2 = 0; n2 < 4; ++n2) {
                uint32_t bf[4];
                uint32_t bd = smem_u32(&Bs[(k16 + (lane & 15)) * BROW
                                           + pw + n2 * 16 + (lane >> 4) * 8]);
                LDSM_X4_T(bf[0], bf[1], bf[2], bf[3], bd);
#pragma unroll
                for (int mt = 0; mt < 4; ++mt) {
                    MMA16816(acc[mt][n2*2][0], acc[mt][n2*2][1],
                             acc[mt][n2*2][2], acc[mt][n2*2][3],
                             a[mt][0], a[mt][1], a[mt][2], a[mt][3],
                             bf[0], bf[1]);
                    MMA16816(acc[mt][n2*2+1][0], acc[mt][n2*2+1][1],
                             acc[mt][n2*2+1][2], acc[mt][n2*2+1][3],
                             a[mt][0], a[mt][1], a[mt][2], a[mt][3],
                             bf[2], bf[3]);
                }
            }
        }
        __syncthreads();
        if (s + 2 < 4)
            gemm_load_stage(sm + (s & 1) * STAGE_ELEMS, s + 2, tid, isK, e0, b, p0);
    }

    float* Out = (isK ? g_k4 : g_q) + (size_t)b * (DKC * PC);
#pragma unroll
    for (int mt = 0; mt < 4; ++mt) {
#pragma unroll
        for (int nt = 0; nt < 8; ++nt) {
            const int r = e0 + ew + mt * 16 + (lane >> 2);
            const int c = p0 + pw + nt * 8 + (lane & 3) * 2;
            *(float2*)&Out[(size_t)r * PC + c] =
                make_float2(acc[mt][nt][0], acc[mt][nt][1]);
            *(float2*)&Out[(size_t)(r + 8) * PC + c] =
                make_float2(acc[mt][nt][2], acc[mt][nt][3]);
        }
    }
}

// ---------------------------------------------------------------------------
// scores phase A (R12-exact): partial dot over half of d.
// grid (64 h, 4 mq, 2 dh), 256 thr = (w 64, mg 4); 2 m x 4 b over 128 d's.
// ---------------------------------------------------------------------------
__global__ __launch_bounds__(256) void scores_partial_kernel(
    const float* __restrict__ kbuf)
{
    __shared__ float qs[32 * 4 * 64];    // [d'][b][w]  32KB

    const int tid = threadIdx.x;
    const int h = blockIdx.x;
    const int mq = blockIdx.y;
    const int dh = blockIdx.z;
    const int w = tid & 63;
    const int mg = tid >> 6;
    const int p = h * 64 + w;
    const int m0 = mq * 8 + mg * 2;
    const int dbase = dh * 128;

    const float* kp[2];
#pragma unroll
    for (int j = 0; j < 2; ++j) {
        const int m = m0 + j;
        kp[j] = ((m < BC) ? g_k4 + (size_t)m * (DKC * PC)
                          : kbuf + (size_t)(m - BC) * (DKC * PC))
                + (size_t)dbase * PC + p;
    }

    float S[4][2];
#pragma unroll
    for (int bb = 0; bb < 4; ++bb) { S[bb][0] = 0.f; S[bb][1] = 0.f; }

    for (int dc = 0; dc < 4; ++dc) {
        __syncthreads();
#pragma unroll
        for (int i = 0; i < 8; ++i) {
            const int flat = (i * 256 + tid) * 4;
            const int d_ = flat >> 8, bb = (flat >> 6) & 3, w0 = flat & 63;
            *(float4*)&qs[flat] = *(const float4*)&g_q[
                ((size_t)(bb * DKC + dbase + dc * 32 + d_)) * PC + h * 64 + w0];
        }
        __syncthreads();
#pragma unroll 8
        for (int d_ = 0; d_ < 32; ++d_) {
            const size_t off = (size_t)(dc * 32 + d_) * PC;
            const float kv0 = kp[0][off];
            const float kv1 = kp[1][off];
#pragma unroll
            for (int bb = 0; bb < 4; ++bb) {
                const float qv = qs[(d_ * 4 + bb) * 64 + w];
                S[bb][0] += qv * kv0;
                S[bb][1] += qv * kv1;
            }
        }
    }

#pragma unroll
    for (int bb = 0; bb < 4; ++bb)
#pragma unroll
        for (int j = 0; j < 2; ++j)
            g_part[(((size_t)dh * BC + bb) * MC + m0 + j) * PC + p] = S[bb][j];
}

// ---------------------------------------------------------------------------
// fused merge + softmax + ctx + blend (R13-proven).
// grid (64 pc, 4 dg): block owns h-row pc and 8 d's. 256 thr = (w 64, dl 4).
// ---------------------------------------------------------------------------
__global__ __launch_bounds__(256) void ctx_softmax_kernel(
    const float* __restrict__ vbuf, const float* __restrict__ fm,
    float* __restrict__ out, float scale)
{
    __shared__ float sS[128 * 65];
    __shared__ float sMx[128], sInv[128];

    const int pc = blockIdx.x, dg = blockIdx.y;
    const int p0 = pc * 64;
    const int tid = threadIdx.x;

#pragma unroll
    for (int i = 0; i < 8; ++i) {
        const int idx = i * 256 + tid;
        const int row = idx >> 4, c4 = (idx & 15) * 4;
        float4 a = *(const float4*)&g_part[(size_t)row * PC + p0 + c4];
        float4 b = *(const float4*)&g_part[(size_t)(128 + row) * PC + p0 + c4];
        float* drow = &sS[row * 65 + c4];
        drow[0] = (a.x + b.x) * scale;
        drow[1] = (a.y + b.y) * scale;
        drow[2] = (a.z + b.z) * scale;
        drow[3] = (a.w + b.w) * scale;
    }
    __syncthreads();

    if (tid < 128) {
        const float* r = &sS[tid * 65];
        float mx = -1e30f;
#pragma unroll
        for (int i = 0; i < 64; ++i) mx = fmaxf(mx, r[i]);
        float s = 0.f;
#pragma unroll
        for (int i = 0; i < 64; ++i) s += __expf(r[i] - mx);
        sMx[tid] = mx; sInv[tid] = 1.f / s;
    }
    __syncthreads();

#pragma unroll
    for (int i = 0; i < 32; ++i) {
        const int idx = i * 256 + tid;
        const int row = idx >> 6, ww = idx & 63;
        sS[row * 65 + ww] = __expf(sS[row * 65 + ww] - sMx[row]) * sInv[row];
    }
    __syncthreads();

    const int w = tid & 63, dl = tid >> 6;
    const int d0 = dg * 8 + dl * 2;
    const int p = p0 + w;

    float c[4][2];
#pragma unroll
    for (int bb = 0; bb < 4; ++bb) { c[bb][0] = 0.f; c[bb][1] = 0.f; }

#pragma unroll
    for (int m = 0; m < MC; ++m) {
        const float* vsrc = (m < BC) ? (g_v4 + (size_t)m * DVC * PC)
                                     : (vbuf + (size_t)(m - BC) * DVC * PC);
        const float vv0 = vsrc[(size_t)d0 * PC + p];
        const float vv1 = vsrc[(size_t)(d0 + 1) * PC + p];
#pragma unroll
        for (int bb = 0; bb < 4; ++bb) {
            const float a = sS[(bb * MC + m) * 65 + w];
            c[bb][0] += a * vv0;
            c[bb][1] += a * vv1;
        }
    }

#pragma unroll
    for (int bb = 0; bb < 4; ++bb)
#pragma unroll
        for (int j = 0; j < 2; ++j) {
            const size_t o = ((size_t)bb * DVC + d0 + j) * PC + p;
            out[o] = fm[o] + 0.5f * c[bb][j];
        }
}

// ---------------------------------------------------------------------------
extern "C" void kernel_launch(void* const* d_in, const int* in_sizes, int n_in,
                              void* d_out, int out_size)
{
    (void)in_sizes; (void)n_in; (void)out_size;
    const float* fc = (const float*)d_in[0];
    const float* fm = (const float*)d_in[1];
    const float* kb = (const float*)d_in[2];
    const float* vb = (const float*)d_in[3];
    const float* Qw = (const float*)d_in[4];
    const float* Kw = (const float*)d_in[5];
    const float* Vw = (const float*)d_in[6];
    float* out = (float*)d_out;

    const float scale = (float)(log(135168.0) / log(1000.0) / 16.0);

    cudaFuncSetAttribute(gemm_hmma_kernel,
                         cudaFuncAttributeMaxDynamicSharedMemorySize,
                         GEMM_SMEM_BYTES);

    prep_kernel<<<2816, 256>>>(fc, Qw, Kw, fm, Vw);
    gemm_hmma_kernel<<<dim3(16, 4, 4), 256, GEMM_SMEM_BYTES>>>();
    scores_partial_kernel<<<dim3(64, 4, 2), 256>>>(kb);
    ctx_softmax_kernel<<<dim3(64, 4), 256>>>(vb, fm, out, scale);
}